// round 12
// baseline (speedup 1.0000x reference)
#include <cuda_runtime.h>
#include <cuda.h>
#include <cuda_fp16.h>
#include <cstdint>
#include <cstddef>

#define HID    1024
#define INTER_ 2816
#define MAX_T  8192
#define NEXP   8

// ---------------------------------------------------------------------------
// Scratch (static device globals; allocation-free rule)
// ---------------------------------------------------------------------------
__device__ __align__(128) __half g_xh[(size_t)MAX_T * HID];          // x fp16 [T][H]
__device__ __align__(128) __half g_wg[(size_t)NEXP * HID * INTER_];  // gate fp16 [E][H][I]
__device__ __align__(128) __half g_wu[(size_t)NEXP * HID * INTER_];  // up fp16   [E][H][I]
__device__ __align__(128) __half g_wd[(size_t)NEXP * HID * INTER_];  // down fp16 [E][I][H]
__device__ __align__(128) __half g_inter[(size_t)MAX_T * INTER_];    // [T][I]
__device__ int g_flags[16];   // [0]=ticket  [1]=xdone  [2+e]=wdone[e]

// ---------------------------------------------------------------------------
// Helpers
// ---------------------------------------------------------------------------
__device__ __forceinline__ uint32_t smem_u32(const void* p) {
    uint32_t a;
    asm("{ .reg .u64 t; cvta.to.shared.u64 t, %1; cvt.u32.u64 %0, t; }" : "=r"(a) : "l"(p));
    return a;
}
__device__ __forceinline__ uint32_t f22u(float a, float b) {
    __half2 h = __floats2half2_rn(a, b);
    return *reinterpret_cast<uint32_t*>(&h);
}

#define CP_ASYNC(sm, gm) \
    asm volatile("cp.async.cg.shared.global [%0], [%1], 16;" :: "r"(sm), "l"(gm))
#define CP_COMMIT() asm volatile("cp.async.commit_group;" ::: "memory")
#define CP_WAIT2()  asm volatile("cp.async.wait_group 2;" ::: "memory")

__device__ __forceinline__ void ldm_x4(uint32_t& r0, uint32_t& r1, uint32_t& r2,
                                       uint32_t& r3, uint32_t addr) {
    asm volatile("ldmatrix.sync.aligned.m8n8.x4.shared.b16 {%0,%1,%2,%3}, [%4];"
                 : "=r"(r0), "=r"(r1), "=r"(r2), "=r"(r3) : "r"(addr));
}
__device__ __forceinline__ void ldm_x4_trans(uint32_t& r0, uint32_t& r1, uint32_t& r2,
                                             uint32_t& r3, uint32_t addr) {
    asm volatile("ldmatrix.sync.aligned.m8n8.x4.trans.shared.b16 {%0,%1,%2,%3}, [%4];"
                 : "=r"(r0), "=r"(r1), "=r"(r2), "=r"(r3) : "r"(addr));
}
__device__ __forceinline__ void mma_f16(float* c, const uint32_t* a, const uint32_t* b) {
    asm volatile(
        "mma.sync.aligned.m16n8k16.row.col.f32.f16.f16.f32 "
        "{%0,%1,%2,%3}, {%4,%5,%6,%7}, {%8,%9}, {%0,%1,%2,%3};"
        : "+f"(c[0]), "+f"(c[1]), "+f"(c[2]), "+f"(c[3])
        : "r"(a[0]), "r"(a[1]), "r"(a[2]), "r"(a[3]), "r"(b[0]), "r"(b[1]));
}

// ---------------------------------------------------------------------------
// Tiling constants (halves).
// ---------------------------------------------------------------------------
#define BK        32
#define STAGES    4
#define ASTRIDE   40
#define BSTR_F    136
#define BSTR_D    264
#define TA_BYTES  (128 * ASTRIDE * 2)        // 10240
#define BF_BYTES  (BK * BSTR_F * 2)          // 8704
#define BD_BYTES  (BK * BSTR_D * 2)          // 16896
#define FS_STAGE  (TA_BYTES + 2 * BF_BYTES)  // 27648
#define DS_STAGE  (TA_BYTES + BD_BYTES)      // 27136

// ---------------------------------------------------------------------------
// Work-list layout for the persistent mega-kernel.
// ---------------------------------------------------------------------------
#define NT_F     (INTER_ / 128)          // 22 n-tiles (fused)
#define MTE      10                      // m-tiles allocated per expert (cnt<=1280)
#define GPE      (MTE * NT_F)            // 220 gemm items / expert
#define NXC      8                       // x convert slices
#define NWC      16                      // gate+up convert slices per expert
#define NDC      8                       // down convert slices per expert block
#define BLK_FULL (NWC + NDC + GPE)       // 244 (blocks e=0..6)
#define BLK_LAST (NDC + GPE)             // 228 (block e=7)
#define NITEMS   (NXC + NWC + 7 * BLK_FULL + BLK_LAST)   // 1960
#define SLICE_F  360448                  // floats per weight-convert slice (H*I/8)

// ---------------------------------------------------------------------------
// fp32 -> fp16 RN slice convert, deep ILP (16 LDG.128 in flight per thread).
// ---------------------------------------------------------------------------
__device__ void cvt_slice(const float* __restrict__ src, __half* __restrict__ dst,
                          int n4, int tid) {
    const float4* in = (const float4*)src;
    uint4* out = (uint4*)dst;
    const int npair = n4 >> 1;
    const int nch = npair >> 11;               // chunks of 2048 pairs
    for (int c = 0; c < nch; ++c) {
        const int base = c * 2048 + tid;
        float4 va[8], vb[8];
        #pragma unroll
        for (int j = 0; j < 8; ++j) {
            int m = base + j * 256;
            va[j] = in[2 * m];
            vb[j] = in[2 * m + 1];
        }
        #pragma unroll
        for (int j = 0; j < 8; ++j) {
            uint4 o;
            o.x = f22u(va[j].x, va[j].y);
            o.y = f22u(va[j].z, va[j].w);
            o.z = f22u(vb[j].x, vb[j].y);
            o.w = f22u(vb[j].z, vb[j].w);
            out[base + j * 256] = o;
        }
    }
    for (int m = (nch << 11) + tid; m < npair; m += 256) {   // tail (usually empty)
        float4 a = in[2 * m], b = in[2 * m + 1];
        uint4 o;
        o.x = f22u(a.x, a.y); o.y = f22u(a.z, a.w);
        o.z = f22u(b.x, b.y); o.w = f22u(b.z, b.w);
        out[m] = o;
    }
}

// ---------------------------------------------------------------------------
// GEMM tile loads (R9, unchanged)
// ---------------------------------------------------------------------------
__device__ __forceinline__ void load_tileA(uint32_t sdst, const __half* g, size_t ld,
                                           int tid, int maxrow) {
    #pragma unroll
    for (int j = 0; j < 2; ++j) {
        int idx = tid + j * 256;
        int r = idx >> 2, c = idx & 3;
        int gr = (r < maxrow) ? r : 0;
        CP_ASYNC(sdst + (r * ASTRIDE + c * 8) * 2, g + (size_t)gr * ld + c * 8);
    }
}
__device__ __forceinline__ void load_tileBF(uint32_t sdst, const __half* g, size_t ld,
                                            int tid) {
    #pragma unroll
    for (int j = 0; j < 2; ++j) {
        int idx = tid + j * 256;
        int r = idx >> 4, c = idx & 15;
        CP_ASYNC(sdst + (r * BSTR_F + c * 8) * 2, g + (size_t)r * ld + c * 8);
    }
}
__device__ __forceinline__ void load_tileBD(uint32_t sdst, const __half* g, size_t ld,
                                            int tid) {
    #pragma unroll
    for (int j = 0; j < 4; ++j) {
        int idx = tid + j * 256;
        int r = idx >> 5, c = idx & 31;
        CP_ASYNC(sdst + (r * BSTR_D + c * 8) * 2, g + (size_t)r * ld + c * 8);
    }
}

// ---------------------------------------------------------------------------
// Fused gate/up compute stage (R9, unchanged)
// ---------------------------------------------------------------------------
__device__ __forceinline__ void compute_stage_fused(
    uint32_t sbase, uint32_t aOff, uint32_t bOff,
    float cg[4][4][4], float cu[4][4][4])
{
    const uint32_t aA = sbase + aOff;
    const uint32_t aG = sbase + TA_BYTES + bOff;
    const uint32_t aU = aG + BF_BYTES;
    #pragma unroll
    for (int ks = 0; ks < 2; ++ks) {
        uint32_t a[4][4];
        #pragma unroll
        for (int mt = 0; mt < 4; ++mt)
            ldm_x4(a[mt][0], a[mt][1], a[mt][2], a[mt][3], aA + ks * 32 + mt * 1280);
        uint32_t bg[4][2], bu[4][2];
        const uint32_t ksb = ks * 16 * BSTR_F * 2;
        #pragma unroll
        for (int p = 0; p < 2; ++p) {
            ldm_x4_trans(bg[2*p][0], bg[2*p][1], bg[2*p+1][0], bg[2*p+1][1],
                         aG + ksb + p * 32);
            ldm_x4_trans(bu[2*p][0], bu[2*p][1], bu[2*p+1][0], bu[2*p+1][1],
                         aU + ksb + p * 32);
        }
        #pragma unroll
        for (int mt = 0; mt < 4; ++mt)
            #pragma unroll
            for (int nt = 0; nt < 4; ++nt) {
                mma_f16(cg[mt][nt], a[mt], bg[nt]);
                mma_f16(cu[mt][nt], a[mt], bu[nt]);
            }
    }
}

// ---------------------------------------------------------------------------
// One fused GEMM+SwiGLU tile (R9 body as a function of (e, start, cnt, m0, n0))
// ---------------------------------------------------------------------------
__device__ void fused_tile(uint32_t sb, __half* smp, int tid,
                           const __half* X, const __half* WG, const __half* WU,
                           __half* OUT, int e, int start, int cnt, int m0, int n0)
{
    const int wid = tid >> 5, lane = tid & 31;
    const int wm = wid & 1, wn = wid >> 1;
    const int rows = min(128, cnt - m0);

    const __half* Ag = X  + (size_t)(start + m0) * HID;
    const __half* Gg = WG + (size_t)e * HID * INTER_ + n0;
    const __half* Ug = WU + (size_t)e * HID * INTER_ + n0;

    const uint32_t aOff = ((wm * 64 + (lane & 15)) * ASTRIDE + (lane >> 4) * 8) * 2;
    const uint32_t bRow = ((lane >> 3) & 1) * 8 + (lane & 7);
    const uint32_t bOff = (bRow * BSTR_F + wn * 32 + (lane >> 4) * 8) * 2;

    float cg[4][4][4], cu[4][4][4];
    #pragma unroll
    for (int a = 0; a < 4; ++a)
        #pragma unroll
        for (int b = 0; b < 4; ++b)
            #pragma unroll
            for (int c = 0; c < 4; ++c) { cg[a][b][c] = 0.f; cu[a][b][c] = 0.f; }

    const int niter = HID / BK;  // 32
    #pragma unroll
    for (int s = 0; s < STAGES - 1; ++s) {
        const uint32_t st = sb + s * FS_STAGE;
        load_tileA (st,                       Ag + s * BK, HID, tid, rows);
        load_tileBF(st + TA_BYTES,            Gg + (size_t)s * BK * INTER_, INTER_, tid);
        load_tileBF(st + TA_BYTES + BF_BYTES, Ug + (size_t)s * BK * INTER_, INTER_, tid);
        CP_COMMIT();
    }
    for (int i = 0; i < niter; ++i) {
        CP_WAIT2();
        __syncthreads();
        compute_stage_fused(sb + (i % STAGES) * FS_STAGE, aOff, bOff, cg, cu);
        const int nb = i + STAGES - 1;
        if (nb < niter) {
            const uint32_t st = sb + (nb % STAGES) * FS_STAGE;
            load_tileA (st,                       Ag + nb * BK, HID, tid, rows);
            load_tileBF(st + TA_BYTES,            Gg + (size_t)nb * BK * INTER_, INTER_, tid);
            load_tileBF(st + TA_BYTES + BF_BYTES, Ug + (size_t)nb * BK * INTER_, INTER_, tid);
        }
        CP_COMMIT();
    }

    const int rbase = wm * 64 + (lane >> 2);
    const int cbase = n0 + wn * 32 + 2 * (lane & 3);
    #pragma unroll
    for (int mt = 0; mt < 4; ++mt) {
        #pragma unroll
        for (int nt = 0; nt < 4; ++nt) {
            const int r0 = rbase + mt * 16;
            const int c  = cbase + nt * 8;
            if (r0 < rows) {
                float a0 = cg[mt][nt][0], a1 = cg[mt][nt][1];
                uint32_t v = f22u(a0 / (1.f + __expf(-a0)) * cu[mt][nt][0],
                                  a1 / (1.f + __expf(-a1)) * cu[mt][nt][1]);
                *(uint32_t*)(OUT + (size_t)(start + m0 + r0) * INTER_ + c) = v;
            }
            if (r0 + 8 < rows) {
                float a2 = cg[mt][nt][2], a3 = cg[mt][nt][3];
                uint32_t v = f22u(a2 / (1.f + __expf(-a2)) * cu[mt][nt][2],
                                  a3 / (1.f + __expf(-a3)) * cu[mt][nt][3]);
                *(uint32_t*)(OUT + (size_t)(start + m0 + r0 + 8) * INTER_ + c) = v;
            }
        }
    }
}

// ---------------------------------------------------------------------------
// Persistent mega-kernel: atomic-ticket work list over
//   [x cvt][e0 cvt] + per-expert blocks of [e+1 cvt | down cvt | gemm tiles].
// Converters flag completion; gemm items spin (deadlock-free: dependencies
// always have lower ticket indices, so they are already assigned to running
// CTAs). cp.async.cg reads are L2-coherent with converter stores + fences.
// ---------------------------------------------------------------------------
__global__ __launch_bounds__(256, 1)
void mega_kernel(const float* __restrict__ x,
                 const float* __restrict__ gate,
                 const float* __restrict__ up,
                 const float* __restrict__ down,
                 const int* __restrict__ tpe, int T)
{
    extern __shared__ __half sm[];
    const uint32_t sb = smem_u32(sm);
    const int tid = threadIdx.x;
    __shared__ int s_item;
    const size_t HI = (size_t)HID * INTER_;

    for (;;) {
        __syncthreads();                       // separates items (smem + s_item)
        if (tid == 0) s_item = atomicAdd(&g_flags[0], 1);
        __syncthreads();
        const int k = s_item;
        if (k >= NITEMS) return;

        if (k < NXC) {                          // x convert slice
            const int n4 = (T * HID / 4) / NXC;
            cvt_slice(x + (size_t)k * n4 * 4, g_xh + (size_t)k * n4 * 4, n4, tid);
            __syncthreads();
            if (tid == 0) { __threadfence(); atomicAdd(&g_flags[1], 1); }
            continue;
        }
        if (k < NXC + NWC) {                    // expert-0 gate/up convert slice
            const int j = k - NXC;
            const float* src = (j < 8 ? gate : up) + (size_t)(j & 7) * SLICE_F;
            __half* dst = (j < 8 ? g_wg : g_wu) + (size_t)(j & 7) * SLICE_F;
            cvt_slice(src, dst, SLICE_F / 4, tid);
            __syncthreads();
            if (tid == 0) { __threadfence(); atomicAdd(&g_flags[2], 1); }
            continue;
        }

        const int k2 = k - (NXC + NWC);
        int e = k2 / BLK_FULL; if (e > 7) e = 7;
        const int r = k2 - e * BLK_FULL;

        if (e < 7 && r < NWC) {                 // expert e+1 gate/up convert slice
            const int ew = e + 1;
            const float* src = (r < 8 ? gate : up) + ew * HI + (size_t)(r & 7) * SLICE_F;
            __half* dst = (r < 8 ? g_wg : g_wu) + ew * HI + (size_t)(r & 7) * SLICE_F;
            cvt_slice(src, dst, SLICE_F / 4, tid);
            __syncthreads();
            if (tid == 0) { __threadfence(); atomicAdd(&g_flags[2 + ew], 1); }
            continue;
        }
        const int r2 = (e < 7) ? r - NWC : r;
        if (r2 < NDC) {                         // down-weight convert slice
            const int s = e * NDC + r2;         // consumed by next launch: no flag
            cvt_slice(down + (size_t)s * SLICE_F, g_wd + (size_t)s * SLICE_F,
                      SLICE_F / 4, tid);
            continue;
        }

        // fused GEMM tile
        const int g = r2 - NDC;
        const int mt = g / NT_F, nt = g % NT_F;
        int start = 0;
        #pragma unroll
        for (int i2 = 0; i2 < NEXP; ++i2) if (i2 < e) start += tpe[i2];
        const int cnt = tpe[e];
        const int m0 = mt * 128;
        if (m0 >= cnt) continue;                // empty tile

        if (tid == 0) {                         // wait for x + this expert's weights
            volatile int* fl = g_flags;
            while (fl[1] < NXC || fl[2 + e] < NWC) __nanosleep(64);
        }
        __syncthreads();

        fused_tile(sb, sm, tid, g_xh, g_wg, g_wu, g_inter,
                   e, start, cnt, m0, nt * 128);
    }
}

// ---------------------------------------------------------------------------
// Down-proj GEMM (R9, unchanged): out(fp32) = inter @ down. CTA 128x256.
// ---------------------------------------------------------------------------
__device__ __forceinline__ void compute_stage_down(
    uint32_t sbase, uint32_t aOff, uint32_t bOff, float cc[4][8][4])
{
    const uint32_t aA = sbase + aOff;
    const uint32_t aB = sbase + TA_BYTES + bOff;
    #pragma unroll
    for (int ks = 0; ks < 2; ++ks) {
        uint32_t a[4][4];
        #pragma unroll
        for (int mt = 0; mt < 4; ++mt)
            ldm_x4(a[mt][0], a[mt][1], a[mt][2], a[mt][3], aA + ks * 32 + mt * 1280);
        uint32_t bf[8][2];
        const uint32_t ksb = ks * 16 * BSTR_D * 2;
        #pragma unroll
        for (int p = 0; p < 4; ++p)
            ldm_x4_trans(bf[2*p][0], bf[2*p][1], bf[2*p+1][0], bf[2*p+1][1],
                         aB + ksb + p * 32);
        #pragma unroll
        for (int mt = 0; mt < 4; ++mt)
            #pragma unroll
            for (int nt = 0; nt < 8; ++nt)
                mma_f16(cc[mt][nt], a[mt], bf[nt]);
    }
}

__global__ __launch_bounds__(256, 1)
void down_proj(const __half* __restrict__ X, const __half* __restrict__ WD,
               float* __restrict__ OUT, const int* __restrict__ tpe)
{
    const int e = blockIdx.z;
    int start = 0;
    #pragma unroll
    for (int i = 0; i < NEXP; ++i) if (i < e) start += tpe[i];
    const int cnt = tpe[e];
    const int m0 = blockIdx.x * 128;
    if (m0 >= cnt) return;
    const int rows = min(128, cnt - m0);
    const int n0 = blockIdx.y * 256;

    extern __shared__ __half sm[];
    const uint32_t sb = smem_u32(sm);
    const int tid = threadIdx.x, wid = tid >> 5, lane = tid & 31;
    const int wm = wid & 1, wn = wid >> 1;

    const __half* Ag = X  + (size_t)(start + m0) * INTER_;
    const __half* Bg = WD + (size_t)e * HID * INTER_ + n0;

    const uint32_t aOff = ((wm * 64 + (lane & 15)) * ASTRIDE + (lane >> 4) * 8) * 2;
    const uint32_t bRow = ((lane >> 3) & 1) * 8 + (lane & 7);
    const uint32_t bOff = (bRow * BSTR_D + wn * 64 + (lane >> 4) * 8) * 2;

    float cc[4][8][4];
    #pragma unroll
    for (int a = 0; a < 4; ++a)
        #pragma unroll
        for (int b = 0; b < 8; ++b)
            #pragma unroll
            for (int c = 0; c < 4; ++c) cc[a][b][c] = 0.f;

    const int niter = INTER_ / BK;  // 88
    #pragma unroll
    for (int s = 0; s < STAGES - 1; ++s) {
        const uint32_t st = sb + s * DS_STAGE;
        load_tileA (st,            Ag + s * BK, INTER_, tid, rows);
        load_tileBD(st + TA_BYTES, Bg + (size_t)s * BK * HID, HID, tid);
        CP_COMMIT();
    }
    for (int i = 0; i < niter; ++i) {
        CP_WAIT2();
        __syncthreads();
        compute_stage_down(sb + (i % STAGES) * DS_STAGE, aOff, bOff, cc);
        const int nb = i + STAGES - 1;
        if (nb < niter) {
            const uint32_t st = sb + (nb % STAGES) * DS_STAGE;
            load_tileA (st,            Ag + nb * BK, INTER_, tid, rows);
            load_tileBD(st + TA_BYTES, Bg + (size_t)nb * BK * HID, HID, tid);
        }
        CP_COMMIT();
    }

    const int rbase = wm * 64 + (lane >> 2);
    const int cbase = n0 + wn * 64 + 2 * (lane & 3);
    #pragma unroll
    for (int mt = 0; mt < 4; ++mt) {
        #pragma unroll
        for (int nt = 0; nt < 8; ++nt) {
            const int r0 = rbase + mt * 16;
            const int c  = cbase + nt * 8;
            if (r0 < rows) {
                float2 v = make_float2(cc[mt][nt][0], cc[mt][nt][1]);
                *reinterpret_cast<float2*>(OUT + (size_t)(start + m0 + r0) * HID + c) = v;
            }
            if (r0 + 8 < rows) {
                float2 v = make_float2(cc[mt][nt][2], cc[mt][nt][3]);
                *reinterpret_cast<float2*>(OUT + (size_t)(start + m0 + r0 + 8) * HID + c) = v;
            }
        }
    }
}

// ---------------------------------------------------------------------------
// Flag reset (plain kernel launch — graph-capturable, no allocations)
// ---------------------------------------------------------------------------
__global__ void zero_flags_kernel() {
    if (threadIdx.x < 16) g_flags[threadIdx.x] = 0;
}

// ---------------------------------------------------------------------------
// Host side: single stream, three plain launches.
// ---------------------------------------------------------------------------
extern "C" void kernel_launch(void* const* d_in, const int* in_sizes, int n_in,
                              void* d_out, int out_size)
{
    const float* x    = (const float*)d_in[0];   // [T, H]
    const float* gate = (const float*)d_in[1];   // [E, H, I]
    const float* up   = (const float*)d_in[2];   // [E, H, I]
    const float* down = (const float*)d_in[3];   // [E, I, H]
    const int*   tpe  = (const int*)d_in[4];     // [E]
    float* out = (float*)d_out;                  // [T, H]

    const int T = in_sizes[0] / HID;

    __half *wd, *inter;
    cudaGetSymbolAddress((void**)&wd, g_wd);
    cudaGetSymbolAddress((void**)&inter, g_inter);

    cudaFuncSetAttribute(mega_kernel, cudaFuncAttributeMaxDynamicSharedMemorySize,
                         STAGES * FS_STAGE);
    cudaFuncSetAttribute(down_proj, cudaFuncAttributeMaxDynamicSharedMemorySize,
                         STAGES * DS_STAGE);

    int sms = 148;
    cudaDeviceGetAttribute(&sms, cudaDevAttrMultiProcessorCount, 0);

    zero_flags_kernel<<<1, 32>>>();
    mega_kernel<<<sms, 256, STAGES * FS_STAGE>>>(x, gate, up, down, tpe, T);

    const int mtiles = (T + 127) / 128;
    dim3 g2(mtiles, HID / 256, NEXP);
    down_proj<<<g2, 256, STAGES * DS_STAGE>>>(inter, wd, out, tpe);
}